// round 9
// baseline (speedup 1.0000x reference)
#include <cuda_runtime.h>

// Fixed shapes: B=8,H=8,L=1024,DK=1024,DV=64; L==DK.
#define NROWS 65536          // B*H*L rows of Q/K, 1024 floats = 256 float4 each

// __device__ globals: zeroed at module load; g_kcs restored to zero by
// finalize_kernel after each consume -> deterministic across graph replays.
__device__ float g_qrs[NROWS];
__device__ float g_krs[NROWS];
__device__ float g_kcs[NROWS];  // colsum, layout [bh][k]

// elu(x)+1 without predicates: max(x,0) + exp(min(x,0))
__device__ __forceinline__ float elu1(float x) {
    return fmaxf(x, 0.0f) + exp2f(fminf(x, 0.0f) * 1.4426950408889634f);
}

// One tile = 32 rows. 8 warps; warp w owns rows 4w..4w+3. Lane ln reads f4
// positions {ln+32j : j<8} of each row via __ldcs (evict-first: data is
// touched exactly once; keep the 512MB stream out of L2 residency).
template <bool DO_COL>
__device__ __forceinline__ void reduce_tile(const float4* __restrict__ X,
                                            int bt, float* __restrict__ rs_out,
                                            float4* __restrict__ scol) {
    const int t  = threadIdx.x;
    const int w  = t >> 5;
    const int ln = t & 31;
    const float4* p = X + (size_t)bt * 8192;     // 32 rows * 256 f4

    float cacc[32];
    if (DO_COL) {
#pragma unroll
        for (int i = 0; i < 32; i++) cacc[i] = 0.0f;
    }

#pragma unroll
    for (int rr = 0; rr < 4; rr++) {
        const int row = w * 4 + rr;
        float4 v[8];
#pragma unroll
        for (int j = 0; j < 8; j++) v[j] = __ldcs(p + row * 256 + ln + 32 * j);

        float s = 0.0f;
#pragma unroll
        for (int j = 0; j < 8; j++) {
            float e0 = elu1(v[j].x), e1 = elu1(v[j].y);
            float e2 = elu1(v[j].z), e3 = elu1(v[j].w);
            if (DO_COL) {
                cacc[4 * j + 0] += e0; cacc[4 * j + 1] += e1;
                cacc[4 * j + 2] += e2; cacc[4 * j + 3] += e3;
            }
            s += (e0 + e1) + (e2 + e3);
        }
        s += __shfl_xor_sync(0xffffffffu, s, 16);
        s += __shfl_xor_sync(0xffffffffu, s, 8);
        s += __shfl_xor_sync(0xffffffffu, s, 4);
        s += __shfl_xor_sync(0xffffffffu, s, 2);
        s += __shfl_xor_sync(0xffffffffu, s, 1);
        if (ln == 0) rs_out[bt * 32 + row] = s;
    }

    if (DO_COL) {
        // Warp w dumps its 32 partials as 8 float4 (conflict-free STS.128).
#pragma unroll
        for (int j = 0; j < 8; j++)
            scol[w * 256 + ln + 32 * j] =
                make_float4(cacc[4 * j], cacc[4 * j + 1],
                            cacc[4 * j + 2], cacc[4 * j + 3]);
        __syncthreads();
        // Thread t combines the 8 warps' partials for f4-column t.
        float4 a = scol[t];
#pragma unroll
        for (int ww = 1; ww < 8; ww++) {
            float4 b = scol[ww * 256 + t];
            a.x += b.x; a.y += b.y; a.z += b.z; a.w += b.w;
        }
        float* base = g_kcs + (bt >> 5) * 1024 + t * 4;
        atomicAdd(base + 0, a.x);
        atomicAdd(base + 1, a.y);
        atomicAdd(base + 2, a.z);
        atomicAdd(base + 3, a.w);
    }
}

__global__ __launch_bounds__(256) void reduce_both_kernel(const float4* __restrict__ K,
                                                          const float4* __restrict__ Q) {
    __shared__ float4 scol[8 * 256];   // 32 KB, used only on the K branch
    const int bt = blockIdx.x;
    if (bt < 2048) reduce_tile<true >(K, bt,        g_krs, scol);
    else           reduce_tile<false>(Q, bt - 2048, g_qrs, scol);
}

// out[row,:] = Qrs*Krs / (Qrs*Kcs + eps) * V[row,:].  1 float4/thread,
// grid 4096 (measured 7.87us).  V read and O write are single-touch ->
// streaming hints.  The 16 readers of a row are one half-warp; the clearing
// STG follows the LDG in program order, so the read-then-clear is race-free.
__global__ __launch_bounds__(256) void finalize_kernel(const float4* __restrict__ V,
                                                       float4* __restrict__ O) {
    const int i   = blockIdx.x * 256 + threadIdx.x;  // float4 index
    const int row = i >> 4;
    const float q = g_qrs[row];
    const float k = g_krs[row];
    const float c = g_kcs[row];
    if ((i & 15) == 0) g_kcs[row] = 0.0f;            // restore for next replay
    const float scale = __fdividef(q * k, fmaf(q, c, 1e-6f));
    float4 v = __ldcs(V + i);
    v.x *= scale; v.y *= scale; v.z *= scale; v.w *= scale;
    __stcs(O + i, v);
}

extern "C" void kernel_launch(void* const* d_in, const int* in_sizes, int n_in,
                              void* d_out, int out_size) {
    const float4* Q = (const float4*)d_in[0];
    const float4* K = (const float4*)d_in[1];
    const float4* V = (const float4*)d_in[2];
    float4* O = (float4*)d_out;

    reduce_both_kernel<<<4096, 256>>>(K, Q);
    finalize_kernel<<<4096, 256>>>(V, O);
}